// round 1
// baseline (speedup 1.0000x reference)
#include <cuda_runtime.h>

#define NN 4
#define C  64
#define H  160
#define W  320
#define DISP 48
#define G  8
#define CG 8
#define HW (H*W)
// smem row stride (floats): 64 + 4 pad. stride % 8 == 4 -> LDS.128/STS.128
// with lanes consecutive in w hit banks {0,4,...,28} within each 8-lane phase:
// conflict-free. stride*4 = 272 B is 16B-aligned so float4 access is legal.
#define SM_STRIDE 68
#define SMEM_BYTES (2 * W * SM_STRIDE * 4)

__global__ __launch_bounds__(512, 1)
void gwc_kernel(const float* __restrict__ lg,
                const float* __restrict__ rg,
                float* __restrict__ out) {
    extern __shared__ float sm[];
    float* l_sm = sm;                  // [W][SM_STRIDE], channel-fastest
    float* r_sm = sm + W * SM_STRIDE;

    const int h   = blockIdx.x;
    const int n   = blockIdx.y;
    const int tid = threadIdx.x;

    const float* lbase = lg + (n * C * H + h) * W;  // + c*HW + w
    const float* rbase = rg + (n * C * H + h) * W;

    // ---- Stage both rows into smem, transposed [w][c] ----
    // Each thread: 4 channels (c4..c4+3) of one w. Global reads coalesced
    // over w; smem store is one STS.128 at w*SM_STRIDE + c4 (conflict-free).
    for (int i = tid; i < (C / 4) * W; i += 512) {
        int w  = i % W;
        int c4 = (i / W) * 4;
        int gbase = c4 * HW + w;
        float4 lv, rv;
        lv.x = lbase[gbase];
        lv.y = lbase[gbase + HW];
        lv.z = lbase[gbase + 2 * HW];
        lv.w = lbase[gbase + 3 * HW];
        rv.x = rbase[gbase];
        rv.y = rbase[gbase + HW];
        rv.z = rbase[gbase + 2 * HW];
        rv.w = rbase[gbase + 3 * HW];
        *(float4*)&l_sm[w * SM_STRIDE + c4] = lv;
        *(float4*)&r_sm[w * SM_STRIDE + c4] = rv;
    }
    __syncthreads();

    // ---- Compute: thread owns (g, w); l channels live in registers,
    // loop over disparity d reading r[w-d] via 2x LDS.128 ----
    for (int item = tid; item < G * W; item += 512) {
        int w = item % W;          // lanes consecutive in w -> coalesced STG
        int g = item / W;
        const float* lp = &l_sm[w * SM_STRIDE + g * CG];
        float4 la = *(const float4*)lp;
        float4 lb = *(const float4*)(lp + 4);
        float* op = out + (((n * G + g) * DISP) * H + h) * W + w;
        const int rb0 = g * CG;

        #pragma unroll 4
        for (int d = 0; d < DISP; ++d) {
            float res = 1.0f;
            if (w >= d) {
                const float* rp = &r_sm[(w - d) * SM_STRIDE + rb0];
                float4 ra = *(const float4*)rp;
                float4 rbv = *(const float4*)(rp + 4);
                float s = la.x * ra.x + la.y * ra.y + la.z * ra.z + la.w * ra.w
                        + lb.x * rbv.x + lb.y * rbv.y + lb.z * rbv.z + lb.w * rbv.w;
                res = s * 0.125f;
            }
            op[d * HW] = res;
        }
    }
}

extern "C" void kernel_launch(void* const* d_in, const int* in_sizes, int n_in,
                              void* d_out, int out_size) {
    const float* l = (const float*)d_in[0];
    const float* r = (const float*)d_in[1];
    float* out = (float*)d_out;

    cudaFuncSetAttribute(gwc_kernel,
                         cudaFuncAttributeMaxDynamicSharedMemorySize,
                         SMEM_BYTES);
    dim3 grid(H, NN);
    gwc_kernel<<<grid, 512, SMEM_BYTES>>>(l, r, out);
}

// round 2
// speedup vs baseline: 1.3912x; 1.3912x over previous
#include <cuda_runtime.h>

#define NN 4
#define C  64
#define H  160
#define W  320
#define DISP 48
#define G  8
#define HW (H*W)
#define ROWB 256                      // bytes per w position (64 floats, no pad)
#define SMEM_BYTES (2 * W * ROWB)     // 160 KB

// XOR-swizzle at 16B granularity within each 128B segment:
// lanes stepping 4 in w get distinct 16B chunks -> conflict-free LDS.128.
__device__ __forceinline__ unsigned sw_off(int w, int colbyte) {
    unsigned off = (unsigned)(w * ROWB + colbyte);
    off ^= (((unsigned)w >> 2) & 7u) << 4;
    return off;
}

#define DOT(j,s) (la[j].x*ra[s].x + la[j].y*ra[s].y + la[j].z*ra[s].z + la[j].w*ra[s].w + \
                  lb4[j].x*rb[s].x + lb4[j].y*rb[s].y + lb4[j].z*rb[s].z + lb4[j].w*rb[s].w)

__global__ __launch_bounds__(640, 1)
void gwc_kernel(const float* __restrict__ lg,
                const float* __restrict__ rg,
                float* __restrict__ out) {
    extern __shared__ char sm[];
    char* lS = sm;                // [W][64 floats], channel-fastest, swizzled
    char* rS = sm + W * ROWB;

    const int h   = blockIdx.x;
    const int n   = blockIdx.y;
    const int tid = threadIdx.x;

    const float* lbase = lg + (n * C * H + h) * W;   // + c*HW + w
    const float* rbase = rg + (n * C * H + h) * W;

    // ---- Stage both rows into smem, transposed [w][c], swizzled ----
    // Global reads coalesced over w (lanes consecutive in w).
    #pragma unroll
    for (int i = tid; i < (C / 4) * W; i += 640) {
        int w  = i % W;
        int c4 = (i / W) * 4;
        int gb = c4 * HW + w;
        float4 lv, rv;
        lv.x = lbase[gb];          rv.x = rbase[gb];
        lv.y = lbase[gb + HW];     rv.y = rbase[gb + HW];
        lv.z = lbase[gb + 2*HW];   rv.z = rbase[gb + 2*HW];
        lv.w = lbase[gb + 3*HW];   rv.w = rbase[gb + 3*HW];
        *(float4*)(lS + sw_off(w, c4 * 4)) = lv;
        *(float4*)(rS + sw_off(w, c4 * 4)) = rv;
    }
    __syncthreads();

    // ---- Compute: one item per thread: (g, w0), w0 = 4*(tid%80), g = tid/80.
    // l channels for w0..w0+3 in registers; r ring of 4 vectors shifted over d.
    const int w0 = (tid % 80) * 4;
    const int g  = tid / 80;
    const int cb = g * 32;            // byte offset of this group's 8 channels

    float4 la[4], lb4[4];             // l vectors for w0+j (two halves)
    float4 ra[4], rb[4];              // r ring: slot = w_idx & 3
    #pragma unroll
    for (int j = 0; j < 4; ++j) {
        la[j]  = *(const float4*)(lS + sw_off(w0 + j, cb));
        lb4[j] = *(const float4*)(lS + sw_off(w0 + j, cb + 16));
        ra[j]  = *(const float4*)(rS + sw_off(w0 + j, cb));
        rb[j]  = *(const float4*)(rS + sw_off(w0 + j, cb + 16));
    }

    float* op = out + (((n * G + g) * DISP) * H + h) * W + w0;

    for (int d4 = 0; d4 < DISP; d4 += 4) {
        #pragma unroll
        for (int e = 0; e < 4; ++e) {
            const int d  = d4 + e;
            const int sn = (4 - e) & 3;           // slot of new vector w0-d
            const int wn = w0 - d;
            if (d > 0 && wn >= 0) {
                ra[sn] = *(const float4*)(rS + sw_off(wn, cb));
                rb[sn] = *(const float4*)(rS + sw_off(wn, cb + 16));
            }
            float4 o;
            o.x = (w0 + 0 >= d) ? DOT(0, (0 - e) & 3) * 0.125f : 1.0f;
            o.y = (w0 + 1 >= d) ? DOT(1, (1 - e) & 3) * 0.125f : 1.0f;
            o.z = (w0 + 2 >= d) ? DOT(2, (2 - e) & 3) * 0.125f : 1.0f;
            o.w = (w0 + 3 >= d) ? DOT(3, (3 - e) & 3) * 0.125f : 1.0f;
            *(float4*)(op + d * HW) = o;
        }
    }
}

extern "C" void kernel_launch(void* const* d_in, const int* in_sizes, int n_in,
                              void* d_out, int out_size) {
    const float* l = (const float*)d_in[0];
    const float* r = (const float*)d_in[1];
    float* out = (float*)d_out;

    cudaFuncSetAttribute(gwc_kernel,
                         cudaFuncAttributeMaxDynamicSharedMemorySize,
                         SMEM_BYTES);
    dim3 grid(H, NN);
    gwc_kernel<<<grid, 640, SMEM_BYTES>>>(l, r, out);
}

// round 3
// speedup vs baseline: 1.5132x; 1.0877x over previous
#include <cuda_runtime.h>

#define NN 4
#define C  64
#define H  160
#define W  320
#define DISP 48
#define G  8
#define HW (H*W)
// CTA covers 2 groups (16 channels). smem row = 16 floats * 4B = 64B per w.
#define ROWB 64
#define SMEM_FLOATS (W * 16)          // 5120 floats = 20KB

// XOR swizzle, 16B granularity: compute lanes step w by 4 -> (w>>2) steps 1
// per lane -> 8-lane LDS.128 phases hit 8 distinct 16B chunks. Bijective
// (XOR bits 4..6 keyed off bits >=8 of the address).
__device__ __forceinline__ unsigned sw_off(int w, int colbyte) {
    unsigned off = (unsigned)(w * ROWB + colbyte);
    off ^= (((unsigned)w >> 2) & 7u) << 4;
    return off;
}

#define DOT(j, s) (lw[0][j]*ra[s].x + lw[1][j]*ra[s].y + lw[2][j]*ra[s].z + lw[3][j]*ra[s].w + \
                   lw[4][j]*rb[s].x + lw[5][j]*rb[s].y + lw[6][j]*rb[s].z + lw[7][j]*rb[s].w)

__global__ __launch_bounds__(160, 4)
void gwc_kernel(const float* __restrict__ lg,
                const float* __restrict__ rg,
                float* __restrict__ out) {
    __shared__ __align__(16) char rS[SMEM_FLOATS * 4];

    const int h   = blockIdx.x;
    const int n   = blockIdx.y;
    const int gp  = blockIdx.z;          // group pair 0..3
    const int tid = threadIdx.x;

    const int gl = tid / 80;             // local group 0/1
    const int g  = gp * 2 + gl;          // global group
    const int w0 = (tid % 80) * 4;

    // ---- Issue l loads FIRST (latency hidden behind staging + sync) ----
    // lw[c][j] = l[channel g*8+c][w0+j]; 8 coalesced LDG.128 per thread.
    const float* lp = lg + ((n * C + g * 8) * H + h) * W + w0;
    float lw[8][4];
    #pragma unroll
    for (int c = 0; c < 8; ++c) {
        float4 t = *(const float4*)(lp + c * HW);
        lw[c][0] = t.x; lw[c][1] = t.y; lw[c][2] = t.z; lw[c][3] = t.w;
    }

    // ---- Stage r channels [gp*16, gp*16+16) into smem, transposed [w][c] ----
    const float* rbase = rg + ((n * C + gp * 16) * H + h) * W;
    #pragma unroll
    for (int i = tid; i < 4 * W; i += 160) {
        int w  = i % W;
        int c4 = (i / W) * 4;
        int gb = c4 * HW + w;
        float4 rv;
        rv.x = rbase[gb];
        rv.y = rbase[gb + HW];
        rv.z = rbase[gb + 2 * HW];
        rv.w = rbase[gb + 3 * HW];
        *(float4*)(rS + sw_off(w, c4 * 4)) = rv;
    }
    __syncthreads();

    // ---- Compute: ring of 4 r-vector-pairs shifted across disparity ----
    const int cb = gl * 32;              // byte offset of this group's 8 ch
    float4 ra[4], rb[4];                 // slot = w_index & 3
    #pragma unroll
    for (int j = 0; j < 4; ++j) {
        ra[j] = *(const float4*)(rS + sw_off(w0 + j, cb));
        rb[j] = *(const float4*)(rS + sw_off(w0 + j, cb + 16));
    }

    float* op = out + (((n * G + g) * DISP) * H + h) * W + w0;

    if (w0 >= DISP) {
        // Fast path: no boundary handling, unconditional ring loads.
        #pragma unroll 4
        for (int d = 0; d < DISP; ++d) {
            const int e  = d & 3;
            const int sn = (4 - e) & 3;
            if (d > 0) {
                const int wn = w0 - d;
                ra[sn] = *(const float4*)(rS + sw_off(wn, cb));
                rb[sn] = *(const float4*)(rS + sw_off(wn, cb + 16));
            }
            float4 o;
            o.x = DOT(0, (0 - e) & 3) * 0.125f;
            o.y = DOT(1, (1 - e) & 3) * 0.125f;
            o.z = DOT(2, (2 - e) & 3) * 0.125f;
            o.w = DOT(3, (3 - e) & 3) * 0.125f;
            __stcs((float4*)(op + d * HW), o);
        }
    } else {
        // Boundary path (w0 < 48): predicate out-of-range columns to 1.0.
        #pragma unroll 4
        for (int d = 0; d < DISP; ++d) {
            const int e  = d & 3;
            const int sn = (4 - e) & 3;
            const int wn = w0 - d;
            if (d > 0 && wn >= 0) {
                ra[sn] = *(const float4*)(rS + sw_off(wn, cb));
                rb[sn] = *(const float4*)(rS + sw_off(wn, cb + 16));
            }
            float4 o;
            o.x = (w0 + 0 >= d) ? DOT(0, (0 - e) & 3) * 0.125f : 1.0f;
            o.y = (w0 + 1 >= d) ? DOT(1, (1 - e) & 3) * 0.125f : 1.0f;
            o.z = (w0 + 2 >= d) ? DOT(2, (2 - e) & 3) * 0.125f : 1.0f;
            o.w = (w0 + 3 >= d) ? DOT(3, (3 - e) & 3) * 0.125f : 1.0f;
            __stcs((float4*)(op + d * HW), o);
        }
    }
}

extern "C" void kernel_launch(void* const* d_in, const int* in_sizes, int n_in,
                              void* d_out, int out_size) {
    const float* l = (const float*)d_in[0];
    const float* r = (const float*)d_in[1];
    float* out = (float*)d_out;

    dim3 grid(H, NN, 4);
    gwc_kernel<<<grid, 160>>>(l, r, out);
}

// round 4
// speedup vs baseline: 1.5857x; 1.0479x over previous
#include <cuda_runtime.h>

#define NN 4
#define C  64
#define H  160
#define W  320
#define DISP 48
#define G  8
#define HW (H*W)
// CTA covers 2 groups (16 channels). smem row = 16 floats * 4B = 64B per w.
#define ROWB 64
#define SMEM_BYTES (W * 16 * 4)       // 20KB

// XOR swizzle, 16B granularity. Compute lanes step w by 2 -> (w>>1) steps 1
// per lane -> 8-lane LDS.128 phases hit 8 distinct 16B chunks: conflict-free.
// Bijective: XORs addr bits [4:7) with addr bits [7:10).
__device__ __forceinline__ unsigned sw_off(int w, int colbyte) {
    unsigned off = (unsigned)(w * ROWB + colbyte);
    off ^= (((unsigned)w >> 1) & 7u) << 4;
    return off;
}

#define DOT(lw, s) (lw[0]*ra[s].x + lw[1]*ra[s].y + lw[2]*ra[s].z + lw[3]*ra[s].w + \
                    lw[4]*rb[s].x + lw[5]*rb[s].y + lw[6]*rb[s].z + lw[7]*rb[s].w)

__global__ __launch_bounds__(320, 3)
void gwc_kernel(const float* __restrict__ lg,
                const float* __restrict__ rg,
                float* __restrict__ out) {
    __shared__ __align__(16) char rS[SMEM_BYTES];

    const int h   = blockIdx.x;
    const int n   = blockIdx.y;
    const int gp  = blockIdx.z;          // group pair 0..3
    const int tid = threadIdx.x;

    const int gl = tid / 160;            // local group 0/1
    const int g  = gp * 2 + gl;          // global group
    const int w0 = (tid % 160) * 2;      // this thread's 2 output columns

    // ---- l loads first: 8 x LDG.64, latency hidden behind staging+sync ----
    const float* lp = lg + ((n * C + g * 8) * H + h) * W + w0;
    float lwA[8], lwB[8];                // channel values at w0, w0+1
    #pragma unroll
    for (int c = 0; c < 8; ++c) {
        float2 t = *(const float2*)(lp + c * HW);
        lwA[c] = t.x; lwB[c] = t.y;
    }

    // ---- Stage r channels [gp*16, gp*16+16) into smem, transposed [w][c] ----
    const float* rbase = rg + ((n * C + gp * 16) * H + h) * W;
    #pragma unroll
    for (int i = tid; i < 4 * W; i += 320) {
        int w  = i % W;
        int c4 = (i / W) * 4;
        int gb = c4 * HW + w;
        float4 rv;
        rv.x = rbase[gb];
        rv.y = rbase[gb + HW];
        rv.z = rbase[gb + 2 * HW];
        rv.w = rbase[gb + 3 * HW];
        *(float4*)(rS + sw_off(w, c4 * 4)) = rv;
    }
    __syncthreads();

    // ---- Compute: 2-slot sliding window over disparity.
    // slot p holds the window position with (w index & 1) == p.
    const int cb = gl * 32;
    float4 ra[2], rb[2];
    ra[0] = *(const float4*)(rS + sw_off(w0, cb));
    rb[0] = *(const float4*)(rS + sw_off(w0, cb + 16));
    ra[1] = *(const float4*)(rS + sw_off(w0 + 1, cb));
    rb[1] = *(const float4*)(rS + sw_off(w0 + 1, cb + 16));

    float* op = out + (((n * G + g) * DISP) * H + h) * W + w0;

    if (w0 >= DISP) {
        #pragma unroll 4
        for (int d2 = 0; d2 < DISP; d2 += 2) {
            #pragma unroll
            for (int e = 0; e < 2; ++e) {
                const int d = d2 + e;
                if (d > 0) {             // new position w0-d, parity e
                    const int wn = w0 - d;
                    ra[e] = *(const float4*)(rS + sw_off(wn, cb));
                    rb[e] = *(const float4*)(rS + sw_off(wn, cb + 16));
                }
                float2 o;
                o.x = DOT(lwA, e) * 0.125f;       // pos w0-d   -> parity e
                o.y = DOT(lwB, 1 - e) * 0.125f;   // pos w0+1-d -> parity e^1
                __stcs((float2*)(op + d * HW), o);
            }
        }
    } else {
        #pragma unroll 4
        for (int d2 = 0; d2 < DISP; d2 += 2) {
            #pragma unroll
            for (int e = 0; e < 2; ++e) {
                const int d  = d2 + e;
                const int wn = w0 - d;
                if (d > 0 && wn >= 0) {
                    ra[e] = *(const float4*)(rS + sw_off(wn, cb));
                    rb[e] = *(const float4*)(rS + sw_off(wn, cb + 16));
                }
                float2 o;
                o.x = (w0     >= d) ? DOT(lwA, e) * 0.125f     : 1.0f;
                o.y = (w0 + 1 >= d) ? DOT(lwB, 1 - e) * 0.125f : 1.0f;
                __stcs((float2*)(op + d * HW), o);
            }
        }
    }
}

extern "C" void kernel_launch(void* const* d_in, const int* in_sizes, int n_in,
                              void* d_out, int out_size) {
    const float* l = (const float*)d_in[0];
    const float* r = (const float*)d_in[1];
    float* out = (float*)d_out;

    dim3 grid(H, NN, 4);
    gwc_kernel<<<grid, 320>>>(l, r, out);
}